// round 4
// baseline (speedup 1.0000x reference)
#include <cuda_runtime.h>
#include <cstdint>

// ---------------------------------------------------------------- problem dims
#define BB   8
#define CC   256
#define HH   64
#define WW   64
#define OO   256
#define TAPS 9
#define KTOT (CC * TAPS)        // 2304
#define PIXI (HH * WW)          // 4096
#define TILE_P 128              // pixels per CTA
#define BKC  32                 // channels per K-chunk
#define NCHUNK (TAPS * (CC / BKC))  // 72
#define NTH  576                // 16 MMA warps + 2 producer warps
#define NCONS 512

// ---------------------------------------------------------------- scratch
__device__ float g_x_nhwc[(size_t)BB * PIXI * CC];   // [b][pix][c]
__device__ float g_wtf[(size_t)OO * KTOT];           // fragment-major weights (tf32 bits)

// ---------------------------------------------------------------- smem layout
// A: 2 bufs x [4 ksteps][16 otiles][32 lanes][4 floats] = 2 x 32768
// B: 2 bufs x [4 ksteps][16 ntiles][32 lanes][2 floats] = 2 x 16384
#define SM_A   0
#define SM_B   (SM_A + 2 * 32768)            // 65536
#define SM_CW  (SM_B + 2 * 16384)            // 98304
#define SM_CI  (SM_CW + TAPS * TILE_P * 16)  // 116736
#define SMEM_SZ (SM_CI + TAPS * TILE_P * 8)  // 125952

// ---------------------------------------------------------------- helpers
__device__ __forceinline__ uint32_t smem_u32(const void* p) {
    uint32_t a;
    asm("{ .reg .u64 t; cvta.to.shared.u64 t, %1; cvt.u32.u64 %0, t; }" : "=r"(a) : "l"(p));
    return a;
}
__device__ __forceinline__ unsigned long long dup2(float a) {
    unsigned long long r;
    asm("mov.b64 %0, {%1, %1};" : "=l"(r) : "f"(a));
    return r;
}
__device__ __forceinline__ unsigned long long mul2(unsigned long long a, unsigned long long b) {
    unsigned long long d;
    asm("mul.rn.f32x2 %0, %1, %2;" : "=l"(d) : "l"(a), "l"(b));
    return d;
}
__device__ __forceinline__ void fma2(unsigned long long& d, unsigned long long a,
                                     unsigned long long b) {
    asm("fma.rn.f32x2 %0, %1, %2, %0;" : "+l"(d) : "l"(a), "l"(b));
}
__device__ __forceinline__ uint32_t to_tf32(float f) {
    uint32_t u;
    asm("cvt.rna.tf32.f32 %0, %1;" : "=r"(u) : "f"(f));
    return u;
}
#define CP_ASYNC16(sa, ga) \
    asm volatile("cp.async.cg.shared.global [%0], [%1], 16;" :: "r"(sa), "l"(ga))
#define CP_COMMIT() asm volatile("cp.async.commit_group;" ::: "memory")
#define CP_WAIT0()  asm volatile("cp.async.wait_group 0;" ::: "memory")

#define BAR_SYNC(id)   asm volatile("bar.sync %0, %1;"   :: "r"(id), "n"(NTH) : "memory")
#define BAR_ARRIVE(id) asm volatile("bar.arrive %0, %1;" :: "r"(id), "n"(NTH) : "memory")
#define MEMBAR_CTA()   asm volatile("membar.cta;" ::: "memory")

__device__ __forceinline__ void mma_tf32(float* d, const uint32_t* a, const uint32_t* b) {
    asm volatile(
        "mma.sync.aligned.m16n8k8.row.col.f32.tf32.tf32.f32 "
        "{%0,%1,%2,%3}, {%4,%5,%6,%7}, {%8,%9}, {%0,%1,%2,%3};"
        : "+f"(d[0]), "+f"(d[1]), "+f"(d[2]), "+f"(d[3])
        : "r"(a[0]), "r"(a[1]), "r"(a[2]), "r"(a[3]), "r"(b[0]), "r"(b[1]));
}

// ---------------------------------------------------------------- transforms
__global__ void xpose_kernel(const float* __restrict__ x) {
    __shared__ float tile[32][33];
    const int p0 = blockIdx.x * 32;
    const int c0 = blockIdx.y * 32;
    const int tx = threadIdx.x, ty = threadIdx.y;
    const int b = p0 >> 12;
    const int pimg = p0 - (b << 12);
    #pragma unroll
    for (int i = 0; i < 4; i++) {
        const int c = c0 + ty + i * 8;
        tile[tx][ty + i * 8] = x[((size_t)(b * CC + c)) * PIXI + pimg + tx];
    }
    __syncthreads();
    #pragma unroll
    for (int i = 0; i < 4; i++) {
        const int pl = ty + i * 8;
        g_x_nhwc[((size_t)(p0 + pl)) * CC + c0 + tx] = tile[pl][tx];
    }
}

// weight -> A-fragment-major (m16n8k8 tf32), pre-converted with cvt.rna.tf32
// layout: [ck=0..71][s=0..3][otile=0..15][lane=0..31][reg=0..3]
__global__ void wposef_kernel(const float* __restrict__ w) {
    const int i = blockIdx.x * 256 + threadIdx.x;
    const int reg   = i & 3;
    const int lane  = (i >> 2) & 31;
    const int otile = (i >> 7) & 15;
    const int s     = (i >> 11) & 3;
    const int ck    = i >> 13;
    const int o  = otile * 16 + (lane >> 2) + (reg & 1) * 8;
    const int k8 = (lane & 3) + (reg >> 1) * 4;
    const int c  = (ck & 7) * 32 + s * 8 + k8;
    const int tap = ck >> 3;
    const float v = w[((size_t)(o * CC + c)) * TAPS + tap];
    g_wtf[i] = __uint_as_float(to_tf32(v));
}

// ---------------------------------------------------------------- main kernel
__global__ void __launch_bounds__(NTH, 1)
dfconv_main(const float* __restrict__ offset, float* __restrict__ out) {
    extern __shared__ char smem[];
    const int tid  = threadIdx.x;
    const int wid  = tid >> 5;
    const int lane = tid & 31;

    const int b     = blockIdx.x >> 5;
    const int pimg0 = (blockIdx.x & 31) * TILE_P;

    float4*  cw = reinterpret_cast<float4*>(smem + SM_CW);
    ushort4* ci = reinterpret_cast<ushort4*>(smem + SM_CI);

    // ---- bilinear coefficients: 9 taps x 128 pixels (all threads help)
    for (int t = tid; t < TAPS * TILE_P; t += NTH) {
        const int k = t >> 7;
        const int p = t & 127;
        const int pimg = pimg0 + p;
        const int h = pimg >> 6;
        const int w = pimg & 63;
        const int ky = k / 3;
        const int kx = k - ky * 3;
        const float dy = offset[((size_t)(b * 18 + k * 2 + 0)) * PIXI + pimg];
        const float dx = offset[((size_t)(b * 18 + k * 2 + 1)) * PIXI + pimg];
        const float py = (float)(h - 1 + ky) + dy;
        const float px = (float)(w - 1 + kx) + dx;
        const float y0f = floorf(py);
        const float x0f = floorf(px);
        const float fy = py - y0f;
        const float fx = px - x0f;
        const int y0 = (int)y0f;
        const int x0 = (int)x0f;
        const bool vy0 = (y0 >= 0) && (y0 <= HH - 1);
        const bool vy1 = (y0 + 1 >= 0) && (y0 + 1 <= HH - 1);
        const bool vx0 = (x0 >= 0) && (x0 <= WW - 1);
        const bool vx1 = (x0 + 1 >= 0) && (x0 + 1 <= WW - 1);
        float4 wv;
        wv.x = (vy0 && vx0) ? (1.f - fy) * (1.f - fx) : 0.f;
        wv.y = (vy0 && vx1) ? (1.f - fy) * fx         : 0.f;
        wv.z = (vy1 && vx0) ? fy * (1.f - fx)         : 0.f;
        wv.w = (vy1 && vx1) ? fy * fx                 : 0.f;
        const int yc0 = min(max(y0,     0), HH - 1);
        const int yc1 = min(max(y0 + 1, 0), HH - 1);
        const int xc0 = min(max(x0,     0), WW - 1);
        const int xc1 = min(max(x0 + 1, 0), WW - 1);
        ushort4 iv;
        iv.x = (unsigned short)(yc0 * WW + xc0);
        iv.y = (unsigned short)(yc0 * WW + xc1);
        iv.z = (unsigned short)(yc1 * WW + xc0);
        iv.w = (unsigned short)(yc1 * WW + xc1);
        cw[t] = wv;
        ci[t] = iv;
    }
    __syncthreads();

    if (wid >= 16) {
        // ================= PRODUCER warps (2) =================
        const int ptid = tid - NCONS;           // 0..63
        const int seg  = ptid & 7;              // 4-channel segment
        const int prow = ptid >> 3;             // 0..7
        const float* xb = g_x_nhwc + (size_t)b * PIXI * CC;
        const int s16  = (seg >> 1) * 16;
        const int rsel = seg & 1;

        for (int ck = 0; ck < NCHUNK; ck++) {
            const int buf = ck & 1;
            if (ck >= 2) BAR_SYNC(3 + buf);      // wait FREE

            // A chunk via cp.async: 32 KB / 64 threads = 512 B each
            {
                const float* src = g_wtf + (size_t)ck * 8192 + ptid * 4;
                const uint32_t dst = smem_u32(smem + SM_A + buf * 32768) + ptid * 16;
                #pragma unroll
                for (int i = 0; i < 32; i++)
                    CP_ASYNC16(dst + i * 1024, src + i * 256);
                CP_COMMIT();
            }

            // gather 128 px x 32 ch of this chunk's tap
            {
                const int tap = ck >> 3;
                const int c0  = (ck & 7) * BKC;
                float* bb = reinterpret_cast<float*>(smem + SM_B + buf * 16384);
                const float* xc = xb + c0 + seg * 4;
                #pragma unroll 4
                for (int pblk = 0; pblk < 16; pblk++) {
                    const int p = pblk * 8 + prow;
                    const float4  wv = cw[tap * TILE_P + p];
                    const ushort4 iv = ci[tap * TILE_P + p];
                    const float4 v00 = *reinterpret_cast<const float4*>(xc + (int)iv.x * CC);
                    const float4 v01 = *reinterpret_cast<const float4*>(xc + (int)iv.y * CC);
                    const float4 v10 = *reinterpret_cast<const float4*>(xc + (int)iv.z * CC);
                    const float4 v11 = *reinterpret_cast<const float4*>(xc + (int)iv.w * CC);
                    const unsigned long long wx = dup2(wv.x), wy = dup2(wv.y);
                    const unsigned long long wz = dup2(wv.z), ww2 = dup2(wv.w);
                    const unsigned long long* a0 = reinterpret_cast<const unsigned long long*>(&v00);
                    const unsigned long long* a1 = reinterpret_cast<const unsigned long long*>(&v01);
                    const unsigned long long* a2 = reinterpret_cast<const unsigned long long*>(&v10);
                    const unsigned long long* a3 = reinterpret_cast<const unsigned long long*>(&v11);
                    unsigned long long s0 = mul2(wx, a0[0]);
                    fma2(s0, wy, a1[0]); fma2(s0, wz, a2[0]); fma2(s0, ww2, a3[0]);
                    unsigned long long s1 = mul2(wx, a0[1]);
                    fma2(s1, wy, a1[1]); fma2(s1, wz, a2[1]); fma2(s1, ww2, a3[1]);
                    const float* sf = reinterpret_cast<const float*>(&s0);
                    const float* sg = reinterpret_cast<const float*>(&s1);
                    const int base = ((s16 + (p >> 3)) * 32 + (p & 7) * 4) * 2 + rsel;
                    bb[base + 0] = __uint_as_float(to_tf32(sf[0]));
                    bb[base + 2] = __uint_as_float(to_tf32(sf[1]));
                    bb[base + 4] = __uint_as_float(to_tf32(sg[0]));
                    bb[base + 6] = __uint_as_float(to_tf32(sg[1]));
                }
            }

            CP_WAIT0();
            MEMBAR_CTA();
            BAR_ARRIVE(1 + buf);                 // signal FULL
        }
        return;
    }

    // ================= CONSUMER warps (16) =================
    const int warp_m = wid >> 2;   // 0..3 -> 64 output rows
    const int warp_n = wid & 3;    // 0..3 -> 32 pixels

    float acc[4][4][4];
    #pragma unroll
    for (int mf = 0; mf < 4; mf++)
        #pragma unroll
        for (int nf = 0; nf < 4; nf++)
            #pragma unroll
            for (int r = 0; r < 4; r++)
                acc[mf][nf][r] = 0.f;

    for (int ck = 0; ck < NCHUNK; ck++) {
        const int buf = ck & 1;
        BAR_SYNC(1 + buf);                       // wait FULL

        const uint32_t* Af = reinterpret_cast<const uint32_t*>(smem + SM_A + buf * 32768);
        const uint32_t* Bf = reinterpret_cast<const uint32_t*>(smem + SM_B + buf * 16384);

        #pragma unroll
        for (int s = 0; s < 4; s++) {
            uint32_t a[4][4];
            uint32_t bq[4][2];
            #pragma unroll
            for (int mf = 0; mf < 4; mf++) {
                const uint4 v = reinterpret_cast<const uint4*>(Af)[(s * 16 + warp_m * 4 + mf) * 32 + lane];
                a[mf][0] = v.x; a[mf][1] = v.y; a[mf][2] = v.z; a[mf][3] = v.w;
            }
            #pragma unroll
            for (int nf = 0; nf < 4; nf++) {
                const uint2 v = reinterpret_cast<const uint2*>(Bf)[(s * 16 + warp_n * 4 + nf) * 32 + lane];
                bq[nf][0] = v.x; bq[nf][1] = v.y;
            }
            #pragma unroll
            for (int mf = 0; mf < 4; mf++)
                #pragma unroll
                for (int nf = 0; nf < 4; nf++)
                    mma_tf32(acc[mf][nf], a[mf], bq[nf]);
        }

        BAR_ARRIVE(3 + buf);                     // signal FREE
    }

    // ---- epilogue
    #pragma unroll
    for (int mf = 0; mf < 4; mf++) {
        const int o = warp_m * 64 + mf * 16 + (lane >> 2);
        float* r0 = out + ((size_t)(b * OO + o)) * PIXI + pimg0 + warp_n * 32 + (lane & 3) * 2;
        float* r1 = r0 + 8 * PIXI;
        #pragma unroll
        for (int nf = 0; nf < 4; nf++) {
            float2 v0 = make_float2(acc[mf][nf][0], acc[mf][nf][1]);
            float2 v1 = make_float2(acc[mf][nf][2], acc[mf][nf][3]);
            *reinterpret_cast<float2*>(r0 + nf * 8) = v0;
            *reinterpret_cast<float2*>(r1 + nf * 8) = v1;
        }
    }
}

// ---------------------------------------------------------------- launcher
extern "C" void kernel_launch(void* const* d_in, const int* in_sizes, int n_in,
                              void* d_out, int out_size) {
    const float* x      = (const float*)d_in[0];
    const float* offset = (const float*)d_in[1];
    const float* weight = (const float*)d_in[2];
    float* out          = (float*)d_out;

    cudaFuncSetAttribute(dfconv_main,
                         cudaFuncAttributeMaxDynamicSharedMemorySize, SMEM_SZ);

    dim3 xg((BB * PIXI) / 32, CC / 32);
    xpose_kernel<<<xg, dim3(32, 8)>>>(x);
    wposef_kernel<<<(OO * KTOT) / 256, 256>>>(weight);
    dfconv_main<<<BB * (PIXI / TILE_P), NTH, SMEM_SZ>>>(offset, out);
}

// round 5
// speedup vs baseline: 3.0001x; 3.0001x over previous
#include <cuda_runtime.h>
#include <cuda_fp16.h>
#include <cstdint>

// ---------------------------------------------------------------- problem dims
#define BB   8
#define CC   256
#define HH   64
#define WW   64
#define OO   256
#define TAPS 9
#define KTOT (CC * TAPS)        // 2304
#define PIXI (HH * WW)          // 4096
#define TILE_P 128              // pixels per CTA
#define BKC  32                 // channels per K-chunk
#define NCHUNK (TAPS * (CC / BKC))  // 72
#define NTH  512

// ---------------------------------------------------------------- scratch
__device__ float    g_x_nhwc[(size_t)BB * PIXI * CC];      // [b][pix][c] fp32
__device__ uint32_t g_wtf[(size_t)OO * KTOT / 2];          // A-frag-major fp16 pairs

// ---------------------------------------------------------------- smem layout
// A: 2 bufs x [2 ksteps][16 otiles][32 lanes][4 u32] = 2 x 16384
// B: 2 bufs x [2 ksteps][16 ntiles][32 lanes][2 u32] = 2 x  8192
#define SM_A   0
#define SM_B   (SM_A + 2 * 16384)            // 32768
#define SM_CW  (SM_B + 2 * 8192)             // 49152
#define SM_CI  (SM_CW + TAPS * TILE_P * 16)  // 67584
#define SMEM_SZ (SM_CI + TAPS * TILE_P * 8)  // 76800

// ---------------------------------------------------------------- helpers
__device__ __forceinline__ uint32_t smem_u32(const void* p) {
    uint32_t a;
    asm("{ .reg .u64 t; cvta.to.shared.u64 t, %1; cvt.u32.u64 %0, t; }" : "=r"(a) : "l"(p));
    return a;
}
__device__ __forceinline__ unsigned long long dup2(float a) {
    unsigned long long r;
    asm("mov.b64 %0, {%1, %1};" : "=l"(r) : "f"(a));
    return r;
}
__device__ __forceinline__ unsigned long long mul2(unsigned long long a, unsigned long long b) {
    unsigned long long d;
    asm("mul.rn.f32x2 %0, %1, %2;" : "=l"(d) : "l"(a), "l"(b));
    return d;
}
__device__ __forceinline__ void fma2(unsigned long long& d, unsigned long long a,
                                     unsigned long long b) {
    asm("fma.rn.f32x2 %0, %1, %2, %0;" : "+l"(d) : "l"(a), "l"(b));
}
#define CP_ASYNC16(sa, ga) \
    asm volatile("cp.async.cg.shared.global [%0], [%1], 16;" :: "r"(sa), "l"(ga))
#define CP_COMMIT() asm volatile("cp.async.commit_group;" ::: "memory")
#define CP_WAIT0()  asm volatile("cp.async.wait_group 0;" ::: "memory")

__device__ __forceinline__ void mma_f16(float* d, const uint32_t* a, const uint32_t* b) {
    asm volatile(
        "mma.sync.aligned.m16n8k16.row.col.f32.f16.f16.f32 "
        "{%0,%1,%2,%3}, {%4,%5,%6,%7}, {%8,%9}, {%0,%1,%2,%3};"
        : "+f"(d[0]), "+f"(d[1]), "+f"(d[2]), "+f"(d[3])
        : "r"(a[0]), "r"(a[1]), "r"(a[2]), "r"(a[3]), "r"(b[0]), "r"(b[1]));
}

// ---------------------------------------------------------------- transforms
__global__ void xpose_kernel(const float* __restrict__ x) {
    __shared__ float tile[32][33];
    const int p0 = blockIdx.x * 32;
    const int c0 = blockIdx.y * 32;
    const int tx = threadIdx.x, ty = threadIdx.y;
    const int b = p0 >> 12;
    const int pimg = p0 - (b << 12);
    #pragma unroll
    for (int i = 0; i < 4; i++) {
        const int c = c0 + ty + i * 8;
        tile[tx][ty + i * 8] = x[((size_t)(b * CC + c)) * PIXI + pimg + tx];
    }
    __syncthreads();
    #pragma unroll
    for (int i = 0; i < 4; i++) {
        const int pl = ty + i * 8;
        g_x_nhwc[((size_t)(p0 + pl)) * CC + c0 + tx] = tile[pl][tx];
    }
}

// weight -> A-fragment-major fp16 (m16n8k16)
// layout: [ck=0..71][s=0..1][otile=0..15][lane=0..31][reg=0..3] (u32 = 2 fp16)
__global__ void wposef_kernel(const float* __restrict__ w) {
    const int i = blockIdx.x * 256 + threadIdx.x;   // < OO*KTOT/2 = 294912
    const int reg   = i & 3;
    const int lane  = (i >> 2) & 31;
    const int otile = (i >> 7) & 15;
    const int s     = (i >> 11) & 1;
    const int ck    = i >> 12;
    const int o   = otile * 16 + (lane >> 2) + (reg & 1) * 8;
    const int k16 = (lane & 3) * 2 + (reg >> 1) * 8;
    const int c   = (ck & 7) * 32 + s * 16 + k16;
    const int tap = ck >> 3;
    const float v0 = w[((size_t)(o * CC + c + 0)) * TAPS + tap];
    const float v1 = w[((size_t)(o * CC + c + 1)) * TAPS + tap];
    const __half2 h = __float22half2_rn(make_float2(v0, v1));
    g_wtf[i] = *reinterpret_cast<const uint32_t*>(&h);
}

// ---------------------------------------------------------------- main kernel
__global__ void __launch_bounds__(NTH, 1)
dfconv_main(const float* __restrict__ offset, float* __restrict__ out) {
    extern __shared__ char smem[];
    const int tid  = threadIdx.x;
    const int wid  = tid >> 5;
    const int lane = tid & 31;

    const int b     = blockIdx.x >> 5;
    const int pimg0 = (blockIdx.x & 31) * TILE_P;

    float4*  cw = reinterpret_cast<float4*>(smem + SM_CW);
    ushort4* ci = reinterpret_cast<ushort4*>(smem + SM_CI);

    // ---- bilinear coefficients: 9 taps x 128 pixels
    for (int t = tid; t < TAPS * TILE_P; t += NTH) {
        const int k = t >> 7;
        const int p = t & 127;
        const int pimg = pimg0 + p;
        const int h = pimg >> 6;
        const int w = pimg & 63;
        const int ky = k / 3;
        const int kx = k - ky * 3;
        const float dy = offset[((size_t)(b * 18 + k * 2 + 0)) * PIXI + pimg];
        const float dx = offset[((size_t)(b * 18 + k * 2 + 1)) * PIXI + pimg];
        const float py = (float)(h - 1 + ky) + dy;
        const float px = (float)(w - 1 + kx) + dx;
        const float y0f = floorf(py);
        const float x0f = floorf(px);
        const float fy = py - y0f;
        const float fx = px - x0f;
        const int y0 = (int)y0f;
        const int x0 = (int)x0f;
        const bool vy0 = (y0 >= 0) && (y0 <= HH - 1);
        const bool vy1 = (y0 + 1 >= 0) && (y0 + 1 <= HH - 1);
        const bool vx0 = (x0 >= 0) && (x0 <= WW - 1);
        const bool vx1 = (x0 + 1 >= 0) && (x0 + 1 <= WW - 1);
        float4 wv;
        wv.x = (vy0 && vx0) ? (1.f - fy) * (1.f - fx) : 0.f;
        wv.y = (vy0 && vx1) ? (1.f - fy) * fx         : 0.f;
        wv.z = (vy1 && vx0) ? fy * (1.f - fx)         : 0.f;
        wv.w = (vy1 && vx1) ? fy * fx                 : 0.f;
        const int yc0 = min(max(y0,     0), HH - 1);
        const int yc1 = min(max(y0 + 1, 0), HH - 1);
        const int xc0 = min(max(x0,     0), WW - 1);
        const int xc1 = min(max(x0 + 1, 0), WW - 1);
        ushort4 iv;
        iv.x = (unsigned short)(yc0 * WW + xc0);
        iv.y = (unsigned short)(yc0 * WW + xc1);
        iv.z = (unsigned short)(yc1 * WW + xc0);
        iv.w = (unsigned short)(yc1 * WW + xc1);
        cw[t] = wv;
        ci[t] = iv;
    }

    const float* xb = g_x_nhwc + (size_t)b * PIXI * CC;
    const int seg = tid & 3;                 // 8-channel segment
    const int p   = tid >> 2;                // pixel 0..127
    const int rsel = seg & 1;
    const int sblk = (seg >> 1) * 16;        // kstep*16 in ntile units

    // gather one chunk (512 threads, 1 sample each = 8 channels)
    auto gather = [&](int ck, int bufsel) {
        const int tap = ck >> 3;
        const int c0  = (ck & 7) * BKC;
        uint32_t* bb = reinterpret_cast<uint32_t*>(smem + SM_B + bufsel * 8192);
        const float* xc = xb + c0 + seg * 8;
        const float4  wv = cw[tap * TILE_P + p];
        const ushort4 iv = ci[tap * TILE_P + p];
        const float4 c00a = *reinterpret_cast<const float4*>(xc + (int)iv.x * CC);
        const float4 c00b = *reinterpret_cast<const float4*>(xc + (int)iv.x * CC + 4);
        const float4 c01a = *reinterpret_cast<const float4*>(xc + (int)iv.y * CC);
        const float4 c01b = *reinterpret_cast<const float4*>(xc + (int)iv.y * CC + 4);
        const float4 c10a = *reinterpret_cast<const float4*>(xc + (int)iv.z * CC);
        const float4 c10b = *reinterpret_cast<const float4*>(xc + (int)iv.z * CC + 4);
        const float4 c11a = *reinterpret_cast<const float4*>(xc + (int)iv.w * CC);
        const float4 c11b = *reinterpret_cast<const float4*>(xc + (int)iv.w * CC + 4);
        const unsigned long long wx = dup2(wv.x), wy = dup2(wv.y);
        const unsigned long long wz = dup2(wv.z), ww2 = dup2(wv.w);
        const unsigned long long* a0 = reinterpret_cast<const unsigned long long*>(&c00a);
        const unsigned long long* a1 = reinterpret_cast<const unsigned long long*>(&c01a);
        const unsigned long long* a2 = reinterpret_cast<const unsigned long long*>(&c10a);
        const unsigned long long* a3 = reinterpret_cast<const unsigned long long*>(&c11a);
        const int base = ((sblk + (p >> 3)) * 32 + (p & 7) * 4) * 2 + rsel;
        #pragma unroll
        for (int j = 0; j < 4; j++) {
            unsigned long long s0;
            if (j < 2) {
                s0 = mul2(wx, a0[j]);
                fma2(s0, wy, a1[j]); fma2(s0, wz, a2[j]); fma2(s0, ww2, a3[j]);
            } else {
                const unsigned long long* b0 = reinterpret_cast<const unsigned long long*>(&c00b);
                const unsigned long long* b1 = reinterpret_cast<const unsigned long long*>(&c01b);
                const unsigned long long* b2 = reinterpret_cast<const unsigned long long*>(&c10b);
                const unsigned long long* b3 = reinterpret_cast<const unsigned long long*>(&c11b);
                s0 = mul2(wx, b0[j - 2]);
                fma2(s0, wy, b1[j - 2]); fma2(s0, wz, b2[j - 2]); fma2(s0, ww2, b3[j - 2]);
            }
            const float* sf = reinterpret_cast<const float*>(&s0);
            const __half2 h = __float22half2_rn(make_float2(sf[0], sf[1]));
            bb[base + j * 2] = *reinterpret_cast<const uint32_t*>(&h);
        }
    };

    // A chunk prefetch: 16 KB, 512 threads x 32 B
    auto a_prefetch = [&](int ck, int bufsel) {
        const uint32_t* src = g_wtf + (size_t)ck * 4096 + tid * 8;
        const uint32_t dst = smem_u32(smem + SM_A + bufsel * 16384) + tid * 32;
        CP_ASYNC16(dst, src);
        CP_ASYNC16(dst + 16, src + 4);
        CP_COMMIT();
    };

    // ---- prologue
    a_prefetch(0, 0);
    __syncthreads();          // coefficients ready before gather
    gather(0, 0);
    CP_WAIT0();
    __syncthreads();

    const int warp_m = wid >> 2;   // 0..3 -> 64 output rows
    const int warp_n = wid & 3;    // 0..3 -> 32 pixels

    float acc[4][4][4];
    #pragma unroll
    for (int mf = 0; mf < 4; mf++)
        #pragma unroll
        for (int nf = 0; nf < 4; nf++)
            #pragma unroll
            for (int r = 0; r < 4; r++)
                acc[mf][nf][r] = 0.f;

    for (int ck = 0; ck < NCHUNK; ck++) {
        const int buf = ck & 1;
        if (ck + 1 < NCHUNK) a_prefetch(ck + 1, buf ^ 1);

        const uint32_t* Af = reinterpret_cast<const uint32_t*>(smem + SM_A + buf * 16384);
        const uint32_t* Bf = reinterpret_cast<const uint32_t*>(smem + SM_B + buf * 8192);

        #pragma unroll
        for (int s = 0; s < 2; s++) {
            uint32_t a[4][4];
            uint32_t bq[4][2];
            #pragma unroll
            for (int mf = 0; mf < 4; mf++) {
                const uint4 v = reinterpret_cast<const uint4*>(Af)[(s * 16 + warp_m * 4 + mf) * 32 + lane];
                a[mf][0] = v.x; a[mf][1] = v.y; a[mf][2] = v.z; a[mf][3] = v.w;
            }
            #pragma unroll
            for (int nf = 0; nf < 4; nf++) {
                const uint2 v = reinterpret_cast<const uint2*>(Bf)[(s * 16 + warp_n * 4 + nf) * 32 + lane];
                bq[nf][0] = v.x; bq[nf][1] = v.y;
            }
            #pragma unroll
            for (int mf = 0; mf < 4; mf++)
                #pragma unroll
                for (int nf = 0; nf < 4; nf++)
                    mma_f16(acc[mf][nf], a[mf], bq[nf]);
        }

        if (ck + 1 < NCHUNK) gather(ck + 1, buf ^ 1);
        CP_WAIT0();
        __syncthreads();
    }

    // ---- epilogue
    #pragma unroll
    for (int mf = 0; mf < 4; mf++) {
        const int o = warp_m * 64 + mf * 16 + (lane >> 2);
        float* r0 = out + ((size_t)(b * OO + o)) * PIXI + pimg0 + warp_n * 32 + (lane & 3) * 2;
        float* r1 = r0 + 8 * PIXI;
        #pragma unroll
        for (int nf = 0; nf < 4; nf++) {
            float2 v0 = make_float2(acc[mf][nf][0], acc[mf][nf][1]);
            float2 v1 = make_float2(acc[mf][nf][2], acc[mf][nf][3]);
            *reinterpret_cast<float2*>(r0 + nf * 8) = v0;
            *reinterpret_cast<float2*>(r1 + nf * 8) = v1;
        }
    }
}

// ---------------------------------------------------------------- launcher
extern "C" void kernel_launch(void* const* d_in, const int* in_sizes, int n_in,
                              void* d_out, int out_size) {
    const float* x      = (const float*)d_in[0];
    const float* offset = (const float*)d_in[1];
    const float* weight = (const float*)d_in[2];
    float* out          = (float*)d_out;

    cudaFuncSetAttribute(dfconv_main,
                         cudaFuncAttributeMaxDynamicSharedMemorySize, SMEM_SZ);

    dim3 xg((BB * PIXI) / 32, CC / 32);
    xpose_kernel<<<xg, dim3(32, 8)>>>(x);
    wposef_kernel<<<(OO * KTOT / 2) / 256, 256>>>(weight);
    dfconv_main<<<BB * (PIXI / TILE_P), NTH, SMEM_SZ>>>(offset, out);
}

// round 6
// speedup vs baseline: 3.8446x; 1.2815x over previous
#include <cuda_runtime.h>
#include <cuda_fp16.h>
#include <cstdint>

// ---------------------------------------------------------------- problem dims
#define BB   8
#define CC   256
#define HH   64
#define WW   64
#define OO   256
#define TAPS 9
#define KTOT (CC * TAPS)        // 2304
#define PIXI (HH * WW)          // 4096
#define TILE_P 128              // pixels per CTA
#define BKC  32                 // channels per K-chunk
#define NCHUNK (TAPS * (CC / BKC))  // 72
#define NTH  512

// ---------------------------------------------------------------- scratch
__device__ __half   g_x_nhwc[(size_t)BB * PIXI * CC];      // [b][pix][c] fp16
__device__ uint32_t g_wtf[(size_t)OO * KTOT / 2];          // A-frag-major fp16 pairs

// ---------------------------------------------------------------- smem layout
// A: 2 bufs x [2 ksteps][16 otiles][32 lanes][4 u32] = 2 x 16384
// B: 2 bufs x [2 ksteps][16 ntiles][32 lanes][2 u32] = 2 x  8192
#define SM_A   0
#define SM_B   (SM_A + 2 * 16384)            // 32768
#define SM_CW  (SM_B + 2 * 8192)             // 49152
#define SM_CI  (SM_CW + TAPS * TILE_P * 16)  // 67584
#define SMEM_SZ (SM_CI + TAPS * TILE_P * 8)  // 76800

// ---------------------------------------------------------------- helpers
__device__ __forceinline__ uint32_t smem_u32(const void* p) {
    uint32_t a;
    asm("{ .reg .u64 t; cvta.to.shared.u64 t, %1; cvt.u32.u64 %0, t; }" : "=r"(a) : "l"(p));
    return a;
}
#define CP_ASYNC16(sa, ga) \
    asm volatile("cp.async.cg.shared.global [%0], [%1], 16;" :: "r"(sa), "l"(ga))
#define CP_COMMIT() asm volatile("cp.async.commit_group;" ::: "memory")
#define CP_WAIT0()  asm volatile("cp.async.wait_group 0;" ::: "memory")

__device__ __forceinline__ void mma_f16(float* d, const uint32_t* a, const uint32_t* b) {
    asm volatile(
        "mma.sync.aligned.m16n8k16.row.col.f32.f16.f16.f32 "
        "{%0,%1,%2,%3}, {%4,%5,%6,%7}, {%8,%9}, {%0,%1,%2,%3};"
        : "+f"(d[0]), "+f"(d[1]), "+f"(d[2]), "+f"(d[3])
        : "r"(a[0]), "r"(a[1]), "r"(a[2]), "r"(a[3]), "r"(b[0]), "r"(b[1]));
}

// ---------------------------------------------------------------- transforms
__global__ void xpose_kernel(const float* __restrict__ x) {
    __shared__ float tile[32][33];
    const int p0 = blockIdx.x * 32;
    const int c0 = blockIdx.y * 32;
    const int tx = threadIdx.x, ty = threadIdx.y;
    const int b = p0 >> 12;
    const int pimg = p0 - (b << 12);
    #pragma unroll
    for (int i = 0; i < 4; i++) {
        const int c = c0 + ty + i * 8;
        tile[tx][ty + i * 8] = x[((size_t)(b * CC + c)) * PIXI + pimg + tx];
    }
    __syncthreads();
    #pragma unroll
    for (int i = 0; i < 4; i++) {
        const int pl = ty + i * 8;
        g_x_nhwc[((size_t)(p0 + pl)) * CC + c0 + tx] = __float2half_rn(tile[pl][tx]);
    }
}

// weight -> A-fragment-major fp16 (m16n8k16)
// layout: [ck=0..71][s=0..1][otile=0..15][lane=0..31][reg=0..3] (u32 = 2 fp16)
__global__ void wposef_kernel(const float* __restrict__ w) {
    const int i = blockIdx.x * 256 + threadIdx.x;   // < OO*KTOT/2 = 294912
    const int reg   = i & 3;
    const int lane  = (i >> 2) & 31;
    const int otile = (i >> 7) & 15;
    const int s     = (i >> 11) & 1;
    const int ck    = i >> 12;
    const int o   = otile * 16 + (lane >> 2) + (reg & 1) * 8;
    const int k16 = (lane & 3) * 2 + (reg >> 1) * 8;
    const int c   = (ck & 7) * 32 + s * 16 + k16;
    const int tap = ck >> 3;
    const float v0 = w[((size_t)(o * CC + c + 0)) * TAPS + tap];
    const float v1 = w[((size_t)(o * CC + c + 1)) * TAPS + tap];
    const __half2 h = __float22half2_rn(make_float2(v0, v1));
    g_wtf[i] = *reinterpret_cast<const uint32_t*>(&h);
}

// ---------------------------------------------------------------- main kernel
__global__ void __launch_bounds__(NTH, 1)
dfconv_main(const float* __restrict__ offset, float* __restrict__ out) {
    extern __shared__ char smem[];
    const int tid  = threadIdx.x;
    const int wid  = tid >> 5;
    const int lane = tid & 31;

    const int b     = blockIdx.x >> 5;
    const int pimg0 = (blockIdx.x & 31) * TILE_P;

    float4*  cw = reinterpret_cast<float4*>(smem + SM_CW);
    ushort4* ci = reinterpret_cast<ushort4*>(smem + SM_CI);

    // ---- bilinear coefficients: 9 taps x 128 pixels
    for (int t = tid; t < TAPS * TILE_P; t += NTH) {
        const int k = t >> 7;
        const int p = t & 127;
        const int pimg = pimg0 + p;
        const int h = pimg >> 6;
        const int w = pimg & 63;
        const int ky = k / 3;
        const int kx = k - ky * 3;
        const float dy = offset[((size_t)(b * 18 + k * 2 + 0)) * PIXI + pimg];
        const float dx = offset[((size_t)(b * 18 + k * 2 + 1)) * PIXI + pimg];
        const float py = (float)(h - 1 + ky) + dy;
        const float px = (float)(w - 1 + kx) + dx;
        const float y0f = floorf(py);
        const float x0f = floorf(px);
        const float fy = py - y0f;
        const float fx = px - x0f;
        const int y0 = (int)y0f;
        const int x0 = (int)x0f;
        const bool vy0 = (y0 >= 0) && (y0 <= HH - 1);
        const bool vy1 = (y0 + 1 >= 0) && (y0 + 1 <= HH - 1);
        const bool vx0 = (x0 >= 0) && (x0 <= WW - 1);
        const bool vx1 = (x0 + 1 >= 0) && (x0 + 1 <= WW - 1);
        float4 wv;
        wv.x = (vy0 && vx0) ? (1.f - fy) * (1.f - fx) : 0.f;
        wv.y = (vy0 && vx1) ? (1.f - fy) * fx         : 0.f;
        wv.z = (vy1 && vx0) ? fy * (1.f - fx)         : 0.f;
        wv.w = (vy1 && vx1) ? fy * fx                 : 0.f;
        const int yc0 = min(max(y0,     0), HH - 1);
        const int yc1 = min(max(y0 + 1, 0), HH - 1);
        const int xc0 = min(max(x0,     0), WW - 1);
        const int xc1 = min(max(x0 + 1, 0), WW - 1);
        ushort4 iv;
        iv.x = (unsigned short)(yc0 * WW + xc0);
        iv.y = (unsigned short)(yc0 * WW + xc1);
        iv.z = (unsigned short)(yc1 * WW + xc0);
        iv.w = (unsigned short)(yc1 * WW + xc1);
        cw[t] = wv;
        ci[t] = iv;
    }

    const __half* xb = g_x_nhwc + (size_t)b * PIXI * CC;
    const int seg = tid & 3;                 // 8-channel segment
    const int p   = tid >> 2;                // pixel 0..127
    const int rsel = seg & 1;
    const int sblk = (seg >> 1) * 16;
    const int bbase = ((sblk + (p >> 3)) * 32 + (p & 7) * 4) * 2 + rsel;
    const __half* xc = xb + seg * 8;

    uint4 gr0, gr1, gr2, gr3;                // corner fp16 values (8 ch each)
    float4 gwv;

    // issue corner loads for chunk ck
    auto gather_load = [&](int ck) {
        const int tap = ck >> 3;
        const int c0  = (ck & 7) * BKC;
        gwv = cw[tap * TILE_P + p];
        const ushort4 iv = ci[tap * TILE_P + p];
        const __half* xcc = xc + c0;
        gr0 = *reinterpret_cast<const uint4*>(xcc + (int)iv.x * CC);
        gr1 = *reinterpret_cast<const uint4*>(xcc + (int)iv.y * CC);
        gr2 = *reinterpret_cast<const uint4*>(xcc + (int)iv.z * CC);
        gr3 = *reinterpret_cast<const uint4*>(xcc + (int)iv.w * CC);
    };

    // interpolate + store B fragments for buffer bufsel
    auto gather_store = [&](int bufsel) {
        uint32_t* bb = reinterpret_cast<uint32_t*>(smem + SM_B + bufsel * 8192);
        const __half2 wx2 = __float2half2_rn(gwv.x);
        const __half2 wy2 = __float2half2_rn(gwv.y);
        const __half2 wz2 = __float2half2_rn(gwv.z);
        const __half2 ww2 = __float2half2_rn(gwv.w);
        const __half2* a0 = reinterpret_cast<const __half2*>(&gr0);
        const __half2* a1 = reinterpret_cast<const __half2*>(&gr1);
        const __half2* a2 = reinterpret_cast<const __half2*>(&gr2);
        const __half2* a3 = reinterpret_cast<const __half2*>(&gr3);
        #pragma unroll
        for (int j = 0; j < 4; j++) {
            __half2 s = __hmul2(wx2, a0[j]);
            s = __hfma2(wy2, a1[j], s);
            s = __hfma2(wz2, a2[j], s);
            s = __hfma2(ww2, a3[j], s);
            bb[bbase + j * 2] = *reinterpret_cast<const uint32_t*>(&s);
        }
    };

    // A chunk prefetch: 16 KB, 512 threads x 32 B
    auto a_prefetch = [&](int ck, int bufsel) {
        const uint32_t* src = g_wtf + (size_t)ck * 4096 + tid * 8;
        const uint32_t dst = smem_u32(smem + SM_A + bufsel * 16384) + tid * 32;
        CP_ASYNC16(dst, src);
        CP_ASYNC16(dst + 16, src + 4);
        CP_COMMIT();
    };

    // ---- prologue
    a_prefetch(0, 0);
    __syncthreads();          // coefficients ready before gather
    gather_load(0);
    gather_store(0);
    CP_WAIT0();
    __syncthreads();

    const int warp_m = wid >> 2;   // 0..3 -> 64 output rows
    const int warp_n = wid & 3;    // 0..3 -> 32 pixels

    float acc[4][4][4];
    #pragma unroll
    for (int mf = 0; mf < 4; mf++)
        #pragma unroll
        for (int nf = 0; nf < 4; nf++)
            #pragma unroll
            for (int r = 0; r < 4; r++)
                acc[mf][nf][r] = 0.f;

    for (int ck = 0; ck < NCHUNK; ck++) {
        const int buf = ck & 1;
        if (ck + 1 < NCHUNK) {
            a_prefetch(ck + 1, buf ^ 1);
            gather_load(ck + 1);       // LDGs in flight during MMA
        }

        const uint32_t* Af = reinterpret_cast<const uint32_t*>(smem + SM_A + buf * 16384);
        const uint32_t* Bf = reinterpret_cast<const uint32_t*>(smem + SM_B + buf * 8192);

        #pragma unroll
        for (int s = 0; s < 2; s++) {
            uint32_t a[4][4];
            uint32_t bq[4][2];
            #pragma unroll
            for (int mf = 0; mf < 4; mf++) {
                const uint4 v = reinterpret_cast<const uint4*>(Af)[(s * 16 + warp_m * 4 + mf) * 32 + lane];
                a[mf][0] = v.x; a[mf][1] = v.y; a[mf][2] = v.z; a[mf][3] = v.w;
            }
            #pragma unroll
            for (int nf = 0; nf < 4; nf++) {
                const uint2 v = reinterpret_cast<const uint2*>(Bf)[(s * 16 + warp_n * 4 + nf) * 32 + lane];
                bq[nf][0] = v.x; bq[nf][1] = v.y;
            }
            #pragma unroll
            for (int mf = 0; mf < 4; mf++)
                #pragma unroll
                for (int nf = 0; nf < 4; nf++)
                    mma_f16(acc[mf][nf], a[mf], bq[nf]);
        }

        if (ck + 1 < NCHUNK) gather_store(buf ^ 1);
        CP_WAIT0();
        __syncthreads();
    }

    // ---- epilogue
    #pragma unroll
    for (int mf = 0; mf < 4; mf++) {
        const int o = warp_m * 64 + mf * 16 + (lane >> 2);
        float* r0 = out + ((size_t)(b * OO + o)) * PIXI + pimg0 + warp_n * 32 + (lane & 3) * 2;
        float* r1 = r0 + 8 * PIXI;
        #pragma unroll
        for (int nf = 0; nf < 4; nf++) {
            float2 v0 = make_float2(acc[mf][nf][0], acc[mf][nf][1]);
            float2 v1 = make_float2(acc[mf][nf][2], acc[mf][nf][3]);
            *reinterpret_cast<float2*>(r0 + nf * 8) = v0;
            *reinterpret_cast<float2*>(r1 + nf * 8) = v1;
        }
    }
}

// ---------------------------------------------------------------- launcher
extern "C" void kernel_launch(void* const* d_in, const int* in_sizes, int n_in,
                              void* d_out, int out_size) {
    const float* x      = (const float*)d_in[0];
    const float* offset = (const float*)d_in[1];
    const float* weight = (const float*)d_in[2];
    float* out          = (float*)d_out;

    cudaFuncSetAttribute(dfconv_main,
                         cudaFuncAttributeMaxDynamicSharedMemorySize, SMEM_SZ);

    dim3 xg((BB * PIXI) / 32, CC / 32);
    xpose_kernel<<<xg, dim3(32, 8)>>>(x);
    wposef_kernel<<<(OO * KTOT / 2) / 256, 256>>>(weight);
    dfconv_main<<<BB * (PIXI / TILE_P), NTH, SMEM_SZ>>>(offset, out);
}